// round 16
// baseline (speedup 1.0000x reference)
#include <cuda_runtime.h>
#include <cuda_bf16.h>
#include <cuda_fp16.h>
#include <cstdint>
#include <math.h>

#define Bsz  2
#define Nseq 2048
#define Dm   512
#define Hh   8
#define DHd  512
#define Ff   4096
#define Mrows 4096   // Bsz*Nseq
#define BH   16      // Bsz*Hh

// ======================= scratch (device globals) ===========================
__device__ __align__(16) __nv_bfloat16 g_Xh[(size_t)Mrows * Dm];
__device__ __align__(16) __nv_bfloat16 g_Xl[(size_t)Mrows * Dm];
__device__ __align__(16) __half        g_X16h[(size_t)Mrows * Dm];
__device__ __align__(16) __half        g_X16l[(size_t)Mrows * Dm];
__device__ __align__(16) __nv_bfloat16 g_WTh[2 * (size_t)Ff * Dm];   // [mode][n][k] Q,K
__device__ __align__(16) __nv_bfloat16 g_WTl[2 * (size_t)Ff * Dm];
__device__ __align__(16) __half        g_WvT16[(size_t)Ff * Dm];     // [n][k] fp16
__device__ __align__(16) __half        g_WoT16[(size_t)Dm * Dm];
__device__ __align__(16) __nv_bfloat16 g_Qh[(size_t)Mrows * Ff];
__device__ __align__(16) __nv_bfloat16 g_Ql[(size_t)Mrows * Ff];
__device__ __align__(16) __nv_bfloat16 g_Kh[(size_t)Mrows * Ff];
__device__ __align__(16) __nv_bfloat16 g_Kl[(size_t)Mrows * Ff];
__device__ __align__(16) __half        g_VT[(size_t)BH * DHd * Nseq]; // [bh][f][tok], fp16
__device__ __align__(16) float         g_S [(size_t)BH * Nseq * Nseq];
__device__ __align__(16) __half        g_Ph[(size_t)BH * Nseq * Nseq];
__device__ __align__(16) __half        g_Pl[(size_t)BH * Nseq * Nseq];
__device__ __align__(16) float         g_YH[(size_t)BH * Nseq * Dm];
__device__ __align__(16) __half        g_G16h[(size_t)Mrows * Dm];
__device__ __align__(16) __half        g_G16l[(size_t)Mrows * Dm];

// ======================= helpers ===========================================
__device__ __forceinline__ uint32_t smem_to_u32(const void* p) {
    uint32_t a;
    asm("{ .reg .u64 t; cvta.to.shared.u64 t, %1; cvt.u32.u64 %0, t; }" : "=r"(a) : "l"(p));
    return a;
}
// SW64 swizzle for 64-byte rows (8 rows x 64B atom)
#define SWZ64(b) ((b) ^ (((b) >> 3) & 0x30))

#define LDSM_X4(r, addr) \
    asm volatile("ldmatrix.sync.aligned.m8n8.x4.shared.b16 {%0,%1,%2,%3}, [%4];" \
        : "=r"((r)[0]), "=r"((r)[1]), "=r"((r)[2]), "=r"((r)[3]) : "r"(addr))

#define MMA_BF16(d, a, b0, b1) \
    asm volatile("mma.sync.aligned.m16n8k16.row.col.f32.bf16.bf16.f32 " \
        "{%0,%1,%2,%3}, {%4,%5,%6,%7}, {%8,%9}, {%0,%1,%2,%3};" \
        : "+f"((d)[0]), "+f"((d)[1]), "+f"((d)[2]), "+f"((d)[3]) \
        : "r"((a)[0]), "r"((a)[1]), "r"((a)[2]), "r"((a)[3]), "r"(b0), "r"(b1))

#define MMA_F16(d, a, b0, b1) \
    asm volatile("mma.sync.aligned.m16n8k16.row.col.f32.f16.f16.f32 " \
        "{%0,%1,%2,%3}, {%4,%5,%6,%7}, {%8,%9}, {%0,%1,%2,%3};" \
        : "+f"((d)[0]), "+f"((d)[1]), "+f"((d)[2]), "+f"((d)[3]) \
        : "r"((a)[0]), "r"((a)[1]), "r"((a)[2]), "r"((a)[3]), "r"(b0), "r"(b1))

#define CP_ASYNC16(dst, src) \
    asm volatile("cp.async.cg.shared.global [%0], [%1], 16;" :: "r"(dst), "l"(src))
#define CP_COMMIT() asm volatile("cp.async.commit_group;")
#define CP_WAIT1()  asm volatile("cp.async.wait_group 1;")
#define CP_WAIT0()  asm volatile("cp.async.wait_group 0;")

// ======================= split helpers ======================================
__device__ __forceinline__ unsigned bf2(float a, float b) {
    return (unsigned)__bfloat16_as_ushort(__float2bfloat16(a)) |
           ((unsigned)__bfloat16_as_ushort(__float2bfloat16(b)) << 16);
}
__device__ __forceinline__ void split_pair(float a, float b, unsigned& h, unsigned& l) {
    __nv_bfloat16 ah = __float2bfloat16(a), bh = __float2bfloat16(b);
    h = (unsigned)__bfloat16_as_ushort(ah) | ((unsigned)__bfloat16_as_ushort(bh) << 16);
    l = bf2(a - __bfloat162float(ah), b - __bfloat162float(bh));
}
__device__ __forceinline__ void split_pair16(float a, float b, unsigned& h, unsigned& l) {
    __half ah = __float2half_rn(a), bh = __float2half_rn(b);
    h = (unsigned)__half_as_ushort(ah) | ((unsigned)__half_as_ushort(bh) << 16);
    __half al = __float2half_rn(a - __half2float(ah));
    __half bl = __float2half_rn(b - __half2float(bh));
    l = (unsigned)__half_as_ushort(al) | ((unsigned)__half_as_ushort(bl) << 16);
}
__device__ __forceinline__ void split1(float a, __nv_bfloat16& h, __nv_bfloat16& l) {
    h = __float2bfloat16(a);
    l = __float2bfloat16(a - __bfloat162float(h));
}

// ======================= mma.sync GEMM core (K-chunk 32, 3-stage) ===========
// C[128x128] = Ah*Bh + Ah*Bl + Al*Bh over K (bf16, 3-pass). Stage 32KB:
// aH|aL|bH|bL (8KB, 64B rows, SW64). 3 stages = 96KB -> 2 CTAs/SM.
// Pipeline: one __syncthreads per chunk; issue(c+2) overwrites stage (c-1)%3.
#define STG32 32768
#define GEMM_SMEM (3 * STG32)

__device__ __forceinline__ void mma_chunk32(uint32_t sst, int lane, int wm, int wn,
                                            float (&acc)[4][4][4]) {
    const uint32_t aH = sst, aL = sst + 8192, bB = sst + 16384, bL = sst + 24576;
#pragma unroll
    for (int kk = 0; kk < 2; kk++) {
        uint32_t bh[2][4], bl[2][4];
        const int brow = wn * 32 + (lane & 7) + ((lane >> 4) << 3);
        const int bcb = kk * 32 + (((lane >> 3) & 1) << 4);
#pragma unroll
        for (int nb = 0; nb < 2; nb++) {
            uint32_t off = SWZ64(((brow + nb * 16) << 6) + bcb);
            LDSM_X4(bh[nb], bB + off);
            LDSM_X4(bl[nb], bL + off);
        }
        const int acb = kk * 32 + ((lane >> 4) << 4);
#pragma unroll
        for (int mi = 0; mi < 4; mi++) {
            uint32_t ah[4], al[4];
            uint32_t off = SWZ64(((wm * 64 + mi * 16 + (lane & 15)) << 6) + acb);
            LDSM_X4(ah, aH + off);
            LDSM_X4(al, aL + off);
#pragma unroll
            for (int ni = 0; ni < 4; ni++) {
                const int nb = ni >> 1, p = (ni & 1) << 1;
                MMA_BF16(acc[mi][ni], ah, bh[nb][p], bh[nb][p + 1]);
                MMA_BF16(acc[mi][ni], ah, bl[nb][p], bl[nb][p + 1]);
                MMA_BF16(acc[mi][ni], al, bh[nb][p], bh[nb][p + 1]);
            }
        }
    }
}

__device__ __forceinline__ void issue_chunk32(
    uint32_t sbase, int c, int t,
    const __nv_bfloat16* Ah, const __nv_bfloat16* Al, size_t sA,
    const __nv_bfloat16* Bh, const __nv_bfloat16* Bl, size_t sB)
{
    const uint32_t sst = sbase + (uint32_t)(c % 3) * STG32;
    const __nv_bfloat16* ah = Ah + (c << 5);
    const __nv_bfloat16* al = Al + (c << 5);
    const __nv_bfloat16* bhp = Bh + (c << 5);
    const __nv_bfloat16* blp = Bl + (c << 5);
#pragma unroll
    for (int i = 0; i < 2; i++) {
        int u = t + (i << 8), r = u >> 2, cu = u & 3;
        uint32_t d = sst + SWZ64((r << 6) + (cu << 4));
        const size_t so = (size_t)r * sA + (cu << 3);
        CP_ASYNC16(d, ah + so);
        CP_ASYNC16(d + 8192, al + so);
    }
#pragma unroll
    for (int i = 0; i < 2; i++) {
        int u = t + (i << 8), r = u >> 2, cu = u & 3;
        uint32_t d = sst + 16384 + SWZ64((r << 6) + (cu << 4));
        const size_t so = (size_t)r * sB + (cu << 3);
        CP_ASYNC16(d, bhp + so);
        CP_ASYNC16(d + 8192, blp + so);
    }
    CP_COMMIT();
}

__device__ __forceinline__ void gemm_mma(
    const __nv_bfloat16* Ah, const __nv_bfloat16* Al, size_t sA,
    const __nv_bfloat16* Bh, const __nv_bfloat16* Bl, size_t sB,
    int K, uint32_t sbase, float (&acc)[4][4][4])
{
    const int t = threadIdx.x;
    const int lane = t & 31, w = t >> 5, wm = w & 1, wn = w >> 1;
#pragma unroll
    for (int mi = 0; mi < 4; mi++)
#pragma unroll
        for (int ni = 0; ni < 4; ni++)
#pragma unroll
            for (int r = 0; r < 4; r++) acc[mi][ni][r] = 0.f;

    const int NC = K >> 5;
    issue_chunk32(sbase, 0, t, Ah, Al, sA, Bh, Bl, sB);
    if (NC > 1) issue_chunk32(sbase, 1, t, Ah, Al, sA, Bh, Bl, sB);
    for (int c = 0; c < NC; c++) {
        if (c + 1 < NC) CP_WAIT1(); else CP_WAIT0();
        __syncthreads();
        if (c + 2 < NC) issue_chunk32(sbase, c + 2, t, Ah, Al, sA, Bh, Bl, sB);
        mma_chunk32(sbase + (uint32_t)(c % 3) * STG32, lane, wm, wn, acc);
    }
}

// ======================= fp16 2-pass core (stage 24KB: Ah|Al|B) =============
// C = (Ah + Al) * B, fp16 operands, fp32 accum. Used by PV, V-proj, out-proj.
#define STG24 24576
#define PV_SMEM (3 * STG24)

__device__ __forceinline__ void mma_chunk32_pv(uint32_t sst, int lane, int wm, int wn,
                                               float (&acc)[4][4][4]) {
    const uint32_t aH = sst, aL = sst + 8192, bB = sst + 16384;
#pragma unroll
    for (int kk = 0; kk < 2; kk++) {
        uint32_t bh[2][4];
        const int brow = wn * 32 + (lane & 7) + ((lane >> 4) << 3);
        const int bcb = kk * 32 + (((lane >> 3) & 1) << 4);
#pragma unroll
        for (int nb = 0; nb < 2; nb++) {
            uint32_t off = SWZ64(((brow + nb * 16) << 6) + bcb);
            LDSM_X4(bh[nb], bB + off);
        }
        const int acb = kk * 32 + ((lane >> 4) << 4);
#pragma unroll
        for (int mi = 0; mi < 4; mi++) {
            uint32_t ah[4], al[4];
            uint32_t off = SWZ64(((wm * 64 + mi * 16 + (lane & 15)) << 6) + acb);
            LDSM_X4(ah, aH + off);
            LDSM_X4(al, aL + off);
#pragma unroll
            for (int ni = 0; ni < 4; ni++) {
                const int nb = ni >> 1, p = (ni & 1) << 1;
                MMA_F16(acc[mi][ni], ah, bh[nb][p], bh[nb][p + 1]);
                MMA_F16(acc[mi][ni], al, bh[nb][p], bh[nb][p + 1]);
            }
        }
    }
}

__device__ __forceinline__ void issue_chunk32_pv(
    uint32_t sbase, int c, int t,
    const __half* Ph, const __half* Pl, size_t sA,
    const __half* Vv, size_t sB)
{
    const uint32_t sst = sbase + (uint32_t)(c % 3) * STG24;
    const __half* ph = Ph + (c << 5);
    const __half* pl = Pl + (c << 5);
    const __half* vp = Vv + (c << 5);
#pragma unroll
    for (int i = 0; i < 2; i++) {
        int u = t + (i << 8), r = u >> 2, cu = u & 3;
        uint32_t d = sst + SWZ64((r << 6) + (cu << 4));
        const size_t so = (size_t)r * sA + (cu << 3);
        CP_ASYNC16(d, ph + so);
        CP_ASYNC16(d + 8192, pl + so);
    }
#pragma unroll
    for (int i = 0; i < 2; i++) {
        int u = t + (i << 8), r = u >> 2, cu = u & 3;
        uint32_t d = sst + 16384 + SWZ64((r << 6) + (cu << 4));
        CP_ASYNC16(d, vp + (size_t)r * sB + (cu << 3));
    }
    CP_COMMIT();
}

__device__ __forceinline__ void gemm_mma_pv(
    const __half* Ph, const __half* Pl, size_t sA,
    const __half* Vv, size_t sB,
    int K, uint32_t sbase, float (&acc)[4][4][4])
{
    const int t = threadIdx.x;
    const int lane = t & 31, w = t >> 5, wm = w & 1, wn = w >> 1;
#pragma unroll
    for (int mi = 0; mi < 4; mi++)
#pragma unroll
        for (int ni = 0; ni < 4; ni++)
#pragma unroll
            for (int r = 0; r < 4; r++) acc[mi][ni][r] = 0.f;

    const int NC = K >> 5;
    issue_chunk32_pv(sbase, 0, t, Ph, Pl, sA, Vv, sB);
    if (NC > 1) issue_chunk32_pv(sbase, 1, t, Ph, Pl, sA, Vv, sB);
    for (int c = 0; c < NC; c++) {
        if (c + 1 < NC) CP_WAIT1(); else CP_WAIT0();
        __syncthreads();
        if (c + 2 < NC) issue_chunk32_pv(sbase, c + 2, t, Ph, Pl, sA, Vv, sB);
        mma_chunk32_pv(sbase + (uint32_t)(c % 3) * STG24, lane, wm, wn, acc);
    }
}

// ======================= prep kernels =======================================
__global__ __launch_bounds__(256) void xc_kernel(const float* __restrict__ x) {
    int i = blockIdx.x * 256 + threadIdx.x;
    float4 v = ((const float4*)x)[i];
    unsigned h0, l0, h1, l1;
    split_pair(v.x, v.y, h0, l0);
    split_pair(v.z, v.w, h1, l1);
    ((uint2*)g_Xh)[i] = make_uint2(h0, h1);
    ((uint2*)g_Xl)[i] = make_uint2(l0, l1);
    split_pair16(v.x, v.y, h0, l0);
    split_pair16(v.z, v.w, h1, l1);
    ((uint2*)g_X16h)[i] = make_uint2(h0, h1);
    ((uint2*)g_X16l)[i] = make_uint2(l0, l1);
}

// merged Wq/Wk transpose (z = 0 -> Wq, 1 -> Wk), bf16 hi/lo
__global__ void wtqk_kernel(const float* __restrict__ Wq,
                            const float* __restrict__ Wk) {
    __shared__ float tile[32][33];
    const int mode = blockIdx.z;
    const float* src = mode ? Wk : Wq;
    __nv_bfloat16* dh = g_WTh + (size_t)mode * Ff * Dm;
    __nv_bfloat16* dl = g_WTl + (size_t)mode * Ff * Dm;
    int n0 = blockIdx.x * 32, k0 = blockIdx.y * 32;
    int tx = threadIdx.x, ty = threadIdx.y;        // ty 0..7
#pragma unroll
    for (int r = 0; r < 4; r++)
        tile[ty + 8 * r][tx] = src[(size_t)(k0 + ty + 8 * r) * Ff + n0 + tx];
    __syncthreads();
#pragma unroll
    for (int r = 0; r < 4; r++) {
        float v = tile[tx][ty + 8 * r];
        __nv_bfloat16 h, l;
        split1(v, h, l);
        size_t di = (size_t)(n0 + ty + 8 * r) * Dm + k0 + tx;
        dh[di] = h; dl[di] = l;
    }
}

// transpose to single fp16 (for Wv, Wo)
__global__ void wt16_kernel(const float* __restrict__ src, __half* dst,
                            int K, int NC) {
    __shared__ float tile[32][33];
    int n0 = blockIdx.x * 32, k0 = blockIdx.y * 32;
    int tx = threadIdx.x, ty = threadIdx.y;        // ty 0..7
#pragma unroll
    for (int r = 0; r < 4; r++)
        tile[ty + 8 * r][tx] = src[(size_t)(k0 + ty + 8 * r) * NC + n0 + tx];
    __syncthreads();
#pragma unroll
    for (int r = 0; r < 4; r++) {
        float v = tile[tx][ty + 8 * r];
        dst[(size_t)(n0 + ty + 8 * r) * K + k0 + tx] = __float2half_rn(v);
    }
}

// ======================= 1a) Q/K projection GEMM + RoPE epilogue ============
__global__ __launch_bounds__(256, 2) void mm_proj_kernel(
    const float* __restrict__ cosr, const float* __restrict__ sinr)
{
    extern __shared__ __align__(128) char smem[];
    uint32_t sb = smem_to_u32(smem);
    const int mode = blockIdx.z;   // 0=Q, 1=K
    const int bm = blockIdx.y * 128, bn = blockIdx.x * 128;
    const __nv_bfloat16* Ah = g_Xh + (size_t)bm * Dm;
    const __nv_bfloat16* Al = g_Xl + (size_t)bm * Dm;
    const __nv_bfloat16* Bh = g_WTh + ((size_t)mode * Ff + bn) * Dm;
    const __nv_bfloat16* Bl = g_WTl + ((size_t)mode * Ff + bn) * Dm;
    float acc[4][4][4];
    gemm_mma(Ah, Al, Dm, Bh, Bl, Dm, Dm, sb, acc);

    const int t = threadIdx.x, lane = t & 31, w = t >> 5, wm = w & 1, wn = w >> 1;
    __nv_bfloat16* OH = (mode == 0) ? g_Qh : g_Kh;
    __nv_bfloat16* OL = (mode == 0) ? g_Ql : g_Kl;
#pragma unroll
    for (int mi = 0; mi < 4; mi++)
#pragma unroll
        for (int ni = 0; ni < 4; ni++) {
            int m0 = bm + wm * 64 + mi * 16 + (lane >> 2);
            int c = bn + wn * 32 + ni * 8 + ((lane & 3) << 1);
#pragma unroll
            for (int half = 0; half < 2; half++) {
                int m = m0 + half * 8;
                int n = m & (Nseq - 1);
                float cr0 = cosr[(size_t)n * Ff + c];
                float sr0 = sinr[(size_t)n * Ff + c];
                float cr1 = cosr[(size_t)n * Ff + c + 1];
                float sr1 = sinr[(size_t)n * Ff + c + 1];
                float e = acc[mi][ni][half * 2];
                float o = acc[mi][ni][half * 2 + 1];
                float oe = e * cr0 - o * sr0;
                float oo = o * cr1 + e * sr1;
                unsigned hw, lw;
                split_pair(oe, oo, hw, lw);
                *(unsigned*)&OH[(size_t)m * Ff + c] = hw;
                *(unsigned*)&OL[(size_t)m * Ff + c] = lw;
            }
        }
}

// ======================= 1b) V projection (fp16 2-pass) + bias + transpose ==
__global__ __launch_bounds__(256, 2) void mm_vproj_kernel(const float* __restrict__ bv)
{
    extern __shared__ __align__(128) char smem[];
    uint32_t sb = smem_to_u32(smem);
    const int bm = blockIdx.y * 128, bn = blockIdx.x * 128;
    const __half* Ah = g_X16h + (size_t)bm * Dm;
    const __half* Al = g_X16l + (size_t)bm * Dm;
    const __half* Bv = g_WvT16 + (size_t)bn * Dm;
    float acc[4][4][4];
    gemm_mma_pv(Ah, Al, Dm, Bv, Dm, Dm, sb, acc);

    const int t = threadIdx.x, lane = t & 31, w = t >> 5, wm = w & 1, wn = w >> 1;
    __syncthreads();                    // all MMAs done -> reuse stage smem
    __half* s16 = (__half*)smem;        // [128 f][136 stride] transposed tile
#pragma unroll
    for (int mi = 0; mi < 4; mi++)
#pragma unroll
        for (int ni = 0; ni < 4; ni++) {
            int ml = wm * 64 + mi * 16 + (lane >> 2);
            int cl = wn * 32 + ni * 8 + ((lane & 3) << 1);
            float b0 = bv[bn + cl], b1 = bv[bn + cl + 1];
#pragma unroll
            for (int half = 0; half < 2; half++) {
                int m2 = ml + half * 8;
                s16[cl * 136 + m2]       = __float2half_rn(acc[mi][ni][half * 2] + b0);
                s16[(cl + 1) * 136 + m2] = __float2half_rn(acc[mi][ni][half * 2 + 1] + b1);
            }
        }
    __syncthreads();
    const int b = bm >> 11, tok0 = bm & (Nseq - 1);
    const int h = bn >> 9, f0 = bn & (DHd - 1);
    __half* dst = g_VT + ((size_t)(b * Hh + h) * DHd + f0) * Nseq + tok0;
#pragma unroll
    for (int i = 0; i < 8; i++) {
        int u = t + (i << 8);           // 0..2047
        int f = u >> 4, mg = (u & 15) << 3;
        uint4 v = *(uint4*)&s16[f * 136 + mg];
        *(uint4*)(dst + (size_t)f * Nseq + mg) = v;
    }
}

// ======================= 2) S = Q K^T (triangular grid) =====================
__global__ __launch_bounds__(256, 2) void mm_score_kernel() {
    // triangular index -> (iy, jx), jx <= iy, iy-major (Q tiles cluster in L2)
    const int idx = blockIdx.x;          // 0..135
    int iy = (int)((sqrtf(8.0f * idx + 1.0f) - 1.0f) * 0.5f);
    while ((iy + 1) * (iy + 2) / 2 <= idx) iy++;
    while (iy * (iy + 1) / 2 > idx) iy--;
    const int jx = idx - iy * (iy + 1) / 2;

    extern __shared__ __align__(128) char smem[];
    uint32_t sb = smem_to_u32(smem);
    const int bh = blockIdx.z, b = bh >> 3, h = bh & 7;
    const int i0 = iy * 128, j0 = jx * 128;
    const __nv_bfloat16* Ah = g_Qh + (size_t)(b * Nseq + i0) * Ff + h * DHd;
    const __nv_bfloat16* Al = g_Ql + (size_t)(b * Nseq + i0) * Ff + h * DHd;
    const __nv_bfloat16* Bh = g_Kh + (size_t)(b * Nseq + j0) * Ff + h * DHd;
    const __nv_bfloat16* Bl = g_Kl + (size_t)(b * Nseq + j0) * Ff + h * DHd;
    float acc[4][4][4];
    gemm_mma(Ah, Al, Ff, Bh, Bl, Ff, DHd, sb, acc);

    const int t = threadIdx.x, lane = t & 31, w = t >> 5, wm = w & 1, wn = w >> 1;
    float* Sp = g_S + (size_t)bh * Nseq * Nseq;
#pragma unroll
    for (int mi = 0; mi < 4; mi++)
#pragma unroll
        for (int ni = 0; ni < 4; ni++) {
            int m = i0 + wm * 64 + mi * 16 + (lane >> 2);
            int nn = j0 + wn * 32 + ni * 8 + ((lane & 3) << 1);
            *(float2*)&Sp[(size_t)m * Nseq + nn] = make_float2(acc[mi][ni][0], acc[mi][ni][1]);
            *(float2*)&Sp[(size_t)(m + 8) * Nseq + nn] = make_float2(acc[mi][ni][2], acc[mi][ni][3]);
        }
}

// ======================= 3) causal row softmax -> P fp16 hi/lo ==============
__global__ __launch_bounds__(256) void softmax_kernel() {
    const int rgl = blockIdx.x;
    const int bh = rgl >> 11, i = rgl & (Nseq - 1);
    const size_t base = (size_t)bh * Nseq * Nseq + (size_t)i * Nseq;
    const float* row = g_S + base;
    const int Lz = ((i >> 7) + 1) << 7;         // row span actually written
    const int t = threadIdx.x;

    float v[8];
    float mx = -1e30f;
    int nit = 0;
#pragma unroll
    for (int it = 0; it < 2; it++) {
        int j = (t << 2) + (it << 10);
        if (j < Lz) {
            float4 x4 = *(const float4*)(row + j);
            v[it * 4 + 0] = (j + 0 <= i) ? x4.x : -1e30f;
            v[it * 4 + 1] = (j + 1 <= i) ? x4.y : -1e30f;
            v[it * 4 + 2] = (j + 2 <= i) ? x4.z : -1e30f;
            v[it * 4 + 3] = (j + 3 <= i) ? x4.w : -1e30f;
#pragma unroll
            for (int q = 0; q < 4; q++) mx = fmaxf(mx, v[it * 4 + q]);
            nit = it + 1;
        }
    }

    __shared__ float red[256];
    red[t] = mx; __syncthreads();
    for (int s = 128; s > 0; s >>= 1) { if (t < s) red[t] = fmaxf(red[t], red[t + s]); __syncthreads(); }
    mx = red[0]; __syncthreads();

    float sum = 0.f;
    for (int it = 0; it < nit; it++)
#pragma unroll
        for (int q = 0; q < 4; q++) {
            float p = (v[it * 4 + q] > -1e29f) ? __expf(v[it * 4 + q] - mx) : 0.f;
            v[it * 4 + q] = p;
            sum += p;
        }
    red[t] = sum; __syncthreads();
    for (int s = 128; s > 0; s >>= 1) { if (t < s) red[t] += red[t + s]; __syncthreads(); }
    const float inv = 1.0f / red[0];

    for (int it = 0; it < nit; it++) {
        int j = (t << 2) + (it << 10);
        float p0 = v[it * 4 + 0] * inv, p1 = v[it * 4 + 1] * inv;
        float p2 = v[it * 4 + 2] * inv, p3 = v[it * 4 + 3] * inv;
        unsigned h01, l01, h23, l23;
        split_pair16(p0, p1, h01, l01);
        split_pair16(p2, p3, h23, l23);
        *(uint2*)&g_Ph[base + j] = make_uint2(h01, h23);
        *(uint2*)&g_Pl[base + j] = make_uint2(l01, l23);
    }
}

// ======================= 4) Yh = P @ V (fp16 2-pass, heavy blocks first) ====
__global__ __launch_bounds__(256, 2) void mm_pv_kernel() {
    extern __shared__ __align__(128) char smem[];
    uint32_t sb = smem_to_u32(smem);
    const int bh = blockIdx.z;
    const int i0 = (15 - blockIdx.y) * 128;     // longest CTAs launch first
    const int n0 = blockIdx.x * 128;
    const __half* Ph = g_Ph + (size_t)bh * Nseq * Nseq + (size_t)i0 * Nseq;
    const __half* Pl = g_Pl + (size_t)bh * Nseq * Nseq + (size_t)i0 * Nseq;
    const __half* Vv = g_VT + (size_t)bh * DHd * Nseq + (size_t)n0 * Nseq;
    float acc[4][4][4];
    gemm_mma_pv(Ph, Pl, Nseq, Vv, Nseq, i0 + 128, sb, acc);

    const int t = threadIdx.x, lane = t & 31, w = t >> 5, wm = w & 1, wn = w >> 1;
    float* Yp = g_YH + (size_t)bh * Nseq * Dm;
#pragma unroll
    for (int mi = 0; mi < 4; mi++)
#pragma unroll
        for (int ni = 0; ni < 4; ni++) {
            int m = i0 + wm * 64 + mi * 16 + (lane >> 2);
            int nn = n0 + wn * 32 + ni * 8 + ((lane & 3) << 1);
            *(float2*)&Yp[(size_t)m * Dm + nn] = make_float2(acc[mi][ni][0], acc[mi][ni][1]);
            *(float2*)&Yp[(size_t)(m + 8) * Dm + nn] = make_float2(acc[mi][ni][2], acc[mi][ni][3]);
        }
}

// ======================= 5) head-sum + QuickGELU + fp16 split ===============
__global__ __launch_bounds__(256) void reduce_kernel() {
    int idx = blockIdx.x * 256 + threadIdx.x;
    int m = idx >> 7;
    int c4 = (idx & 127) * 4;
    int b = m >> 11, n = m & (Nseq - 1);
    float4 s = make_float4(0.f, 0.f, 0.f, 0.f);
#pragma unroll
    for (int h = 0; h < Hh; h++) {
        const float4 v = *(const float4*)(g_YH + (size_t)((b * Hh + h) * Nseq + n) * Dm + c4);
        s.x += v.x; s.y += v.y; s.z += v.z; s.w += v.w;
    }
    s.x = s.x / (1.f + __expf(-1.702f * s.x));
    s.y = s.y / (1.f + __expf(-1.702f * s.y));
    s.z = s.z / (1.f + __expf(-1.702f * s.z));
    s.w = s.w / (1.f + __expf(-1.702f * s.w));
    unsigned h0, l0, h1, l1;
    split_pair16(s.x, s.y, h0, l0);
    split_pair16(s.z, s.w, h1, l1);
    *(uint2*)(g_G16h + (size_t)m * Dm + c4) = make_uint2(h0, h1);
    *(uint2*)(g_G16l + (size_t)m * Dm + c4) = make_uint2(l0, l1);
}

// ======================= 6) output projection (fp16 2-pass) =================
__global__ __launch_bounds__(256, 2) void mm_out_kernel(const float* __restrict__ bo,
                                                        float* __restrict__ Outp) {
    extern __shared__ __align__(128) char smem[];
    uint32_t sb = smem_to_u32(smem);
    const int bm = blockIdx.y * 128, bn = blockIdx.x * 128;
    const __half* Ah = g_G16h + (size_t)bm * Dm;
    const __half* Al = g_G16l + (size_t)bm * Dm;
    const __half* Bo = g_WoT16 + (size_t)bn * Dm;
    float acc[4][4][4];
    gemm_mma_pv(Ah, Al, Dm, Bo, Dm, Dm, sb, acc);

    const int t = threadIdx.x, lane = t & 31, w = t >> 5, wm = w & 1, wn = w >> 1;
#pragma unroll
    for (int mi = 0; mi < 4; mi++)
#pragma unroll
        for (int ni = 0; ni < 4; ni++) {
            int m = bm + wm * 64 + mi * 16 + (lane >> 2);
            int c = bn + wn * 32 + ni * 8 + ((lane & 3) << 1);
            float b0 = bo[c], b1 = bo[c + 1];
            *(float2*)&Outp[(size_t)m * Dm + c] =
                make_float2(acc[mi][ni][0] + b0, acc[mi][ni][1] + b1);
            *(float2*)&Outp[(size_t)(m + 8) * Dm + c] =
                make_float2(acc[mi][ni][2] + b0, acc[mi][ni][3] + b1);
        }
}

// ======================= launch =============================================
extern "C" void kernel_launch(void* const* d_in, const int* in_sizes, int n_in,
                              void* d_out, int out_size)
{
    const float* x    = (const float*)d_in[0];
    const float* cosr = (const float*)d_in[1];
    const float* sinr = (const float*)d_in[2];
    // d_in[3] = target_mask (causal tril; handled analytically)
    const float* Wq   = (const float*)d_in[4];
    const float* Wk   = (const float*)d_in[5];
    const float* Wv   = (const float*)d_in[6];
    const float* bv   = (const float*)d_in[7];
    const float* Wo   = (const float*)d_in[8];
    const float* bo   = (const float*)d_in[9];
    float* out = (float*)d_out;

    cudaFuncSetAttribute(mm_proj_kernel,  cudaFuncAttributeMaxDynamicSharedMemorySize, GEMM_SMEM);
    cudaFuncSetAttribute(mm_vproj_kernel, cudaFuncAttributeMaxDynamicSharedMemorySize, PV_SMEM);
    cudaFuncSetAttribute(mm_score_kernel, cudaFuncAttributeMaxDynamicSharedMemorySize, GEMM_SMEM);
    cudaFuncSetAttribute(mm_pv_kernel,    cudaFuncAttributeMaxDynamicSharedMemorySize, PV_SMEM);
    cudaFuncSetAttribute(mm_out_kernel,   cudaFuncAttributeMaxDynamicSharedMemorySize, PV_SMEM);

    __half *wvt16, *wot16;
    cudaGetSymbolAddress((void**)&wvt16, g_WvT16);
    cudaGetSymbolAddress((void**)&wot16, g_WoT16);

    xc_kernel<<<2048, 256>>>(x);
    wtqk_kernel<<<dim3(128, 16, 2), dim3(32, 8)>>>(Wq, Wk);
    wt16_kernel<<<dim3(128, 16), dim3(32, 8)>>>(Wv, wvt16, Dm, Ff);
    wt16_kernel<<<dim3(16, 16), dim3(32, 8)>>>(Wo, wot16, Dm, Dm);
    mm_proj_kernel<<<dim3(32, 32, 2), 256, GEMM_SMEM>>>(cosr, sinr);
    mm_vproj_kernel<<<dim3(32, 32), 256, PV_SMEM>>>(bv);
    mm_score_kernel<<<dim3(136, 1, BH), 256, GEMM_SMEM>>>();
    softmax_kernel<<<BH * Nseq, 256>>>();
    mm_pv_kernel<<<dim3(4, 16, BH), 256, PV_SMEM>>>();
    reduce_kernel<<<2048, 256>>>();
    mm_out_kernel<<<dim3(4, 32), 256, PV_SMEM>>>(bo, out);
}

// round 17
// speedup vs baseline: 1.0534x; 1.0534x over previous
#include <cuda_runtime.h>
#include <cuda_bf16.h>
#include <cuda_fp16.h>
#include <cstdint>
#include <math.h>

#define Bsz  2
#define Nseq 2048
#define Dm   512
#define Hh   8
#define DHd  512
#define Ff   4096
#define Mrows 4096   // Bsz*Nseq
#define BH   16      // Bsz*Hh

// ======================= scratch (device globals) ===========================
__device__ __align__(16) __nv_bfloat16 g_Xh[(size_t)Mrows * Dm];
__device__ __align__(16) __nv_bfloat16 g_Xl[(size_t)Mrows * Dm];
__device__ __align__(16) __half        g_X16h[(size_t)Mrows * Dm];
__device__ __align__(16) __nv_bfloat16 g_WTh[2 * (size_t)Ff * Dm];   // [mode][n][k] Q,K
__device__ __align__(16) __nv_bfloat16 g_WTl[2 * (size_t)Ff * Dm];
__device__ __align__(16) __half        g_WvT16[(size_t)Ff * Dm];     // [n][k] fp16
__device__ __align__(16) __half        g_WoT16[(size_t)Dm * Dm];
__device__ __align__(16) __nv_bfloat16 g_Qh[(size_t)Mrows * Ff];
__device__ __align__(16) __nv_bfloat16 g_Ql[(size_t)Mrows * Ff];
__device__ __align__(16) __nv_bfloat16 g_Kh[(size_t)Mrows * Ff];
__device__ __align__(16) __nv_bfloat16 g_Kl[(size_t)Mrows * Ff];
__device__ __align__(16) __half        g_VT[(size_t)BH * DHd * Nseq]; // [bh][f][tok], fp16
__device__ __align__(16) float         g_S [(size_t)BH * Nseq * Nseq];
__device__ __align__(16) __half        g_Ph[(size_t)BH * Nseq * Nseq];
__device__ __align__(16) __half        g_Pl[(size_t)BH * Nseq * Nseq];
__device__ __align__(16) float         g_YH[(size_t)BH * Nseq * Dm];
__device__ __align__(16) __half        g_G16h[(size_t)Mrows * Dm];

// ======================= helpers ===========================================
__device__ __forceinline__ uint32_t smem_to_u32(const void* p) {
    uint32_t a;
    asm("{ .reg .u64 t; cvta.to.shared.u64 t, %1; cvt.u32.u64 %0, t; }" : "=r"(a) : "l"(p));
    return a;
}
// SW64 swizzle for 64-byte rows (8 rows x 64B atom)
#define SWZ64(b) ((b) ^ (((b) >> 3) & 0x30))

#define LDSM_X4(r, addr) \
    asm volatile("ldmatrix.sync.aligned.m8n8.x4.shared.b16 {%0,%1,%2,%3}, [%4];" \
        : "=r"((r)[0]), "=r"((r)[1]), "=r"((r)[2]), "=r"((r)[3]) : "r"(addr))

#define MMA_BF16(d, a, b0, b1) \
    asm volatile("mma.sync.aligned.m16n8k16.row.col.f32.bf16.bf16.f32 " \
        "{%0,%1,%2,%3}, {%4,%5,%6,%7}, {%8,%9}, {%0,%1,%2,%3};" \
        : "+f"((d)[0]), "+f"((d)[1]), "+f"((d)[2]), "+f"((d)[3]) \
        : "r"((a)[0]), "r"((a)[1]), "r"((a)[2]), "r"((a)[3]), "r"(b0), "r"(b1))

#define MMA_F16(d, a, b0, b1) \
    asm volatile("mma.sync.aligned.m16n8k16.row.col.f32.f16.f16.f32 " \
        "{%0,%1,%2,%3}, {%4,%5,%6,%7}, {%8,%9}, {%0,%1,%2,%3};" \
        : "+f"((d)[0]), "+f"((d)[1]), "+f"((d)[2]), "+f"((d)[3]) \
        : "r"((a)[0]), "r"((a)[1]), "r"((a)[2]), "r"((a)[3]), "r"(b0), "r"(b1))

#define CP_ASYNC16(dst, src) \
    asm volatile("cp.async.cg.shared.global [%0], [%1], 16;" :: "r"(dst), "l"(src))
#define CP_COMMIT() asm volatile("cp.async.commit_group;")
#define CP_WAIT1()  asm volatile("cp.async.wait_group 1;")
#define CP_WAIT0()  asm volatile("cp.async.wait_group 0;")

// ======================= split helpers ======================================
__device__ __forceinline__ unsigned bf2(float a, float b) {
    return (unsigned)__bfloat16_as_ushort(__float2bfloat16(a)) |
           ((unsigned)__bfloat16_as_ushort(__float2bfloat16(b)) << 16);
}
__device__ __forceinline__ void split_pair(float a, float b, unsigned& h, unsigned& l) {
    __nv_bfloat16 ah = __float2bfloat16(a), bh = __float2bfloat16(b);
    h = (unsigned)__bfloat16_as_ushort(ah) | ((unsigned)__bfloat16_as_ushort(bh) << 16);
    l = bf2(a - __bfloat162float(ah), b - __bfloat162float(bh));
}
__device__ __forceinline__ unsigned pack16(float a, float b) {
    __half ah = __float2half_rn(a), bh = __float2half_rn(b);
    return (unsigned)__half_as_ushort(ah) | ((unsigned)__half_as_ushort(bh) << 16);
}
__device__ __forceinline__ void split_pair16(float a, float b, unsigned& h, unsigned& l) {
    __half ah = __float2half_rn(a), bh = __float2half_rn(b);
    h = (unsigned)__half_as_ushort(ah) | ((unsigned)__half_as_ushort(bh) << 16);
    __half al = __float2half_rn(a - __half2float(ah));
    __half bl = __float2half_rn(b - __half2float(bh));
    l = (unsigned)__half_as_ushort(al) | ((unsigned)__half_as_ushort(bl) << 16);
}
__device__ __forceinline__ void split1(float a, __nv_bfloat16& h, __nv_bfloat16& l) {
    h = __float2bfloat16(a);
    l = __float2bfloat16(a - __bfloat162float(h));
}

// ======================= mma.sync GEMM core (K-chunk 32, 3-stage) ===========
// C[128x128] = Ah*Bh + Ah*Bl + Al*Bh over K (bf16, 3-pass). Stage 32KB:
// aH|aL|bH|bL (8KB, 64B rows, SW64). 3 stages = 96KB -> 2 CTAs/SM.
// Pipeline: one __syncthreads per chunk; issue(c+2) overwrites stage (c-1)%3.
#define STG32 32768
#define GEMM_SMEM (3 * STG32)

__device__ __forceinline__ void mma_chunk32(uint32_t sst, int lane, int wm, int wn,
                                            float (&acc)[4][4][4]) {
    const uint32_t aH = sst, aL = sst + 8192, bB = sst + 16384, bL = sst + 24576;
#pragma unroll
    for (int kk = 0; kk < 2; kk++) {
        uint32_t bh[2][4], bl[2][4];
        const int brow = wn * 32 + (lane & 7) + ((lane >> 4) << 3);
        const int bcb = kk * 32 + (((lane >> 3) & 1) << 4);
#pragma unroll
        for (int nb = 0; nb < 2; nb++) {
            uint32_t off = SWZ64(((brow + nb * 16) << 6) + bcb);
            LDSM_X4(bh[nb], bB + off);
            LDSM_X4(bl[nb], bL + off);
        }
        const int acb = kk * 32 + ((lane >> 4) << 4);
#pragma unroll
        for (int mi = 0; mi < 4; mi++) {
            uint32_t ah[4], al[4];
            uint32_t off = SWZ64(((wm * 64 + mi * 16 + (lane & 15)) << 6) + acb);
            LDSM_X4(ah, aH + off);
            LDSM_X4(al, aL + off);
#pragma unroll
            for (int ni = 0; ni < 4; ni++) {
                const int nb = ni >> 1, p = (ni & 1) << 1;
                MMA_BF16(acc[mi][ni], ah, bh[nb][p], bh[nb][p + 1]);
                MMA_BF16(acc[mi][ni], ah, bl[nb][p], bl[nb][p + 1]);
                MMA_BF16(acc[mi][ni], al, bh[nb][p], bh[nb][p + 1]);
            }
        }
    }
}

__device__ __forceinline__ void issue_chunk32(
    uint32_t sbase, int c, int t,
    const __nv_bfloat16* Ah, const __nv_bfloat16* Al, size_t sA,
    const __nv_bfloat16* Bh, const __nv_bfloat16* Bl, size_t sB)
{
    const uint32_t sst = sbase + (uint32_t)(c % 3) * STG32;
    const __nv_bfloat16* ah = Ah + (c << 5);
    const __nv_bfloat16* al = Al + (c << 5);
    const __nv_bfloat16* bhp = Bh + (c << 5);
    const __nv_bfloat16* blp = Bl + (c << 5);
#pragma unroll
    for (int i = 0; i < 2; i++) {
        int u = t + (i << 8), r = u >> 2, cu = u & 3;
        uint32_t d = sst + SWZ64((r << 6) + (cu << 4));
        const size_t so = (size_t)r * sA + (cu << 3);
        CP_ASYNC16(d, ah + so);
        CP_ASYNC16(d + 8192, al + so);
    }
#pragma unroll
    for (int i = 0; i < 2; i++) {
        int u = t + (i << 8), r = u >> 2, cu = u & 3;
        uint32_t d = sst + 16384 + SWZ64((r << 6) + (cu << 4));
        const size_t so = (size_t)r * sB + (cu << 3);
        CP_ASYNC16(d, bhp + so);
        CP_ASYNC16(d + 8192, blp + so);
    }
    CP_COMMIT();
}

__device__ __forceinline__ void gemm_mma(
    const __nv_bfloat16* Ah, const __nv_bfloat16* Al, size_t sA,
    const __nv_bfloat16* Bh, const __nv_bfloat16* Bl, size_t sB,
    int K, uint32_t sbase, float (&acc)[4][4][4])
{
    const int t = threadIdx.x;
    const int lane = t & 31, w = t >> 5, wm = w & 1, wn = w >> 1;
#pragma unroll
    for (int mi = 0; mi < 4; mi++)
#pragma unroll
        for (int ni = 0; ni < 4; ni++)
#pragma unroll
            for (int r = 0; r < 4; r++) acc[mi][ni][r] = 0.f;

    const int NC = K >> 5;
    issue_chunk32(sbase, 0, t, Ah, Al, sA, Bh, Bl, sB);
    if (NC > 1) issue_chunk32(sbase, 1, t, Ah, Al, sA, Bh, Bl, sB);
    for (int c = 0; c < NC; c++) {
        if (c + 1 < NC) CP_WAIT1(); else CP_WAIT0();
        __syncthreads();
        if (c + 2 < NC) issue_chunk32(sbase, c + 2, t, Ah, Al, sA, Bh, Bl, sB);
        mma_chunk32(sbase + (uint32_t)(c % 3) * STG32, lane, wm, wn, acc);
    }
}

// ======================= fp16 2-pass core (stage 24KB: Ah|Al|B) =============
// C = (Ah + Al) * B, fp16 operands, fp32 accum. Used by PV.
#define STG24 24576
#define PV_SMEM (3 * STG24)

__device__ __forceinline__ void mma_chunk32_pv(uint32_t sst, int lane, int wm, int wn,
                                               float (&acc)[4][4][4]) {
    const uint32_t aH = sst, aL = sst + 8192, bB = sst + 16384;
#pragma unroll
    for (int kk = 0; kk < 2; kk++) {
        uint32_t bh[2][4];
        const int brow = wn * 32 + (lane & 7) + ((lane >> 4) << 3);
        const int bcb = kk * 32 + (((lane >> 3) & 1) << 4);
#pragma unroll
        for (int nb = 0; nb < 2; nb++) {
            uint32_t off = SWZ64(((brow + nb * 16) << 6) + bcb);
            LDSM_X4(bh[nb], bB + off);
        }
        const int acb = kk * 32 + ((lane >> 4) << 4);
#pragma unroll
        for (int mi = 0; mi < 4; mi++) {
            uint32_t ah[4], al[4];
            uint32_t off = SWZ64(((wm * 64 + mi * 16 + (lane & 15)) << 6) + acb);
            LDSM_X4(ah, aH + off);
            LDSM_X4(al, aL + off);
#pragma unroll
            for (int ni = 0; ni < 4; ni++) {
                const int nb = ni >> 1, p = (ni & 1) << 1;
                MMA_F16(acc[mi][ni], ah, bh[nb][p], bh[nb][p + 1]);
                MMA_F16(acc[mi][ni], al, bh[nb][p], bh[nb][p + 1]);
            }
        }
    }
}

__device__ __forceinline__ void issue_chunk32_pv(
    uint32_t sbase, int c, int t,
    const __half* Ph, const __half* Pl, size_t sA,
    const __half* Vv, size_t sB)
{
    const uint32_t sst = sbase + (uint32_t)(c % 3) * STG24;
    const __half* ph = Ph + (c << 5);
    const __half* pl = Pl + (c << 5);
    const __half* vp = Vv + (c << 5);
#pragma unroll
    for (int i = 0; i < 2; i++) {
        int u = t + (i << 8), r = u >> 2, cu = u & 3;
        uint32_t d = sst + SWZ64((r << 6) + (cu << 4));
        const size_t so = (size_t)r * sA + (cu << 3);
        CP_ASYNC16(d, ph + so);
        CP_ASYNC16(d + 8192, pl + so);
    }
#pragma unroll
    for (int i = 0; i < 2; i++) {
        int u = t + (i << 8), r = u >> 2, cu = u & 3;
        uint32_t d = sst + 16384 + SWZ64((r << 6) + (cu << 4));
        CP_ASYNC16(d, vp + (size_t)r * sB + (cu << 3));
    }
    CP_COMMIT();
}

__device__ __forceinline__ void gemm_mma_pv(
    const __half* Ph, const __half* Pl, size_t sA,
    const __half* Vv, size_t sB,
    int K, uint32_t sbase, float (&acc)[4][4][4])
{
    const int t = threadIdx.x;
    const int lane = t & 31, w = t >> 5, wm = w & 1, wn = w >> 1;
#pragma unroll
    for (int mi = 0; mi < 4; mi++)
#pragma unroll
        for (int ni = 0; ni < 4; ni++)
#pragma unroll
            for (int r = 0; r < 4; r++) acc[mi][ni][r] = 0.f;

    const int NC = K >> 5;
    issue_chunk32_pv(sbase, 0, t, Ph, Pl, sA, Vv, sB);
    if (NC > 1) issue_chunk32_pv(sbase, 1, t, Ph, Pl, sA, Vv, sB);
    for (int c = 0; c < NC; c++) {
        if (c + 1 < NC) CP_WAIT1(); else CP_WAIT0();
        __syncthreads();
        if (c + 2 < NC) issue_chunk32_pv(sbase, c + 2, t, Ph, Pl, sA, Vv, sB);
        mma_chunk32_pv(sbase + (uint32_t)(c % 3) * STG24, lane, wm, wn, acc);
    }
}

// ======================= fp16 single-pass core (stage 16KB: A|B) ============
// C = A * B, fp16 operands, fp32 accum. Used by V-proj, out-proj.
#define STG16 16384
#define P1_SMEM (3 * STG16)

__device__ __forceinline__ void mma_chunk32_1p(uint32_t sst, int lane, int wm, int wn,
                                               float (&acc)[4][4][4]) {
    const uint32_t aA = sst, bB = sst + 8192;
#pragma unroll
    for (int kk = 0; kk < 2; kk++) {
        uint32_t bh[2][4];
        const int brow = wn * 32 + (lane & 7) + ((lane >> 4) << 3);
        const int bcb = kk * 32 + (((lane >> 3) & 1) << 4);
#pragma unroll
        for (int nb = 0; nb < 2; nb++) {
            uint32_t off = SWZ64(((brow + nb * 16) << 6) + bcb);
            LDSM_X4(bh[nb], bB + off);
        }
        const int acb = kk * 32 + ((lane >> 4) << 4);
#pragma unroll
        for (int mi = 0; mi < 4; mi++) {
            uint32_t ah[4];
            uint32_t off = SWZ64(((wm * 64 + mi * 16 + (lane & 15)) << 6) + acb);
            LDSM_X4(ah, aA + off);
#pragma unroll
            for (int ni = 0; ni < 4; ni++) {
                const int nb = ni >> 1, p = (ni & 1) << 1;
                MMA_F16(acc[mi][ni], ah, bh[nb][p], bh[nb][p + 1]);
            }
        }
    }
}

__device__ __forceinline__ void issue_chunk32_1p(
    uint32_t sbase, int c, int t,
    const __half* Aa, size_t sA, const __half* Bb, size_t sB)
{
    const uint32_t sst = sbase + (uint32_t)(c % 3) * STG16;
    const __half* ap = Aa + (c << 5);
    const __half* bp = Bb + (c << 5);
#pragma unroll
    for (int i = 0; i < 2; i++) {
        int u = t + (i << 8), r = u >> 2, cu = u & 3;
        uint32_t d = sst + SWZ64((r << 6) + (cu << 4));
        CP_ASYNC16(d, ap + (size_t)r * sA + (cu << 3));
        CP_ASYNC16(d + 8192, bp + (size_t)r * sB + (cu << 3));
    }
    CP_COMMIT();
}

__device__ __forceinline__ void gemm_mma_1p(
    const __half* Aa, size_t sA, const __half* Bb, size_t sB,
    int K, uint32_t sbase, float (&acc)[4][4][4])
{
    const int t = threadIdx.x;
    const int lane = t & 31, w = t >> 5, wm = w & 1, wn = w >> 1;
#pragma unroll
    for (int mi = 0; mi < 4; mi++)
#pragma unroll
        for (int ni = 0; ni < 4; ni++)
#pragma unroll
            for (int r = 0; r < 4; r++) acc[mi][ni][r] = 0.f;

    const int NC = K >> 5;
    issue_chunk32_1p(sbase, 0, t, Aa, sA, Bb, sB);
    if (NC > 1) issue_chunk32_1p(sbase, 1, t, Aa, sA, Bb, sB);
    for (int c = 0; c < NC; c++) {
        if (c + 1 < NC) CP_WAIT1(); else CP_WAIT0();
        __syncthreads();
        if (c + 2 < NC) issue_chunk32_1p(sbase, c + 2, t, Aa, sA, Bb, sB);
        mma_chunk32_1p(sbase + (uint32_t)(c % 3) * STG16, lane, wm, wn, acc);
    }
}

// ======================= prep kernels =======================================
__global__ __launch_bounds__(256) void xc_kernel(const float* __restrict__ x) {
    int i = blockIdx.x * 256 + threadIdx.x;
    float4 v = ((const float4*)x)[i];
    unsigned h0, l0, h1, l1;
    split_pair(v.x, v.y, h0, l0);
    split_pair(v.z, v.w, h1, l1);
    ((uint2*)g_Xh)[i] = make_uint2(h0, h1);
    ((uint2*)g_Xl)[i] = make_uint2(l0, l1);
    ((uint2*)g_X16h)[i] = make_uint2(pack16(v.x, v.y), pack16(v.z, v.w));
}

// merged Wq/Wk transpose (z = 0 -> Wq, 1 -> Wk), bf16 hi/lo
__global__ void wtqk_kernel(const float* __restrict__ Wq,
                            const float* __restrict__ Wk) {
    __shared__ float tile[32][33];
    const int mode = blockIdx.z;
    const float* src = mode ? Wk : Wq;
    __nv_bfloat16* dh = g_WTh + (size_t)mode * Ff * Dm;
    __nv_bfloat16* dl = g_WTl + (size_t)mode * Ff * Dm;
    int n0 = blockIdx.x * 32, k0 = blockIdx.y * 32;
    int tx = threadIdx.x, ty = threadIdx.y;        // ty 0..7
#pragma unroll
    for (int r = 0; r < 4; r++)
        tile[ty + 8 * r][tx] = src[(size_t)(k0 + ty + 8 * r) * Ff + n0 + tx];
    __syncthreads();
#pragma unroll
    for (int r = 0; r < 4; r++) {
        float v = tile[tx][ty + 8 * r];
        __nv_bfloat16 h, l;
        split1(v, h, l);
        size_t di = (size_t)(n0 + ty + 8 * r) * Dm + k0 + tx;
        dh[di] = h; dl[di] = l;
    }
}

// transpose to single fp16 (for Wv, Wo)
__global__ void wt16_kernel(const float* __restrict__ src, __half* dst,
                            int K, int NC) {
    __shared__ float tile[32][33];
    int n0 = blockIdx.x * 32, k0 = blockIdx.y * 32;
    int tx = threadIdx.x, ty = threadIdx.y;        // ty 0..7
#pragma unroll
    for (int r = 0; r < 4; r++)
        tile[ty + 8 * r][tx] = src[(size_t)(k0 + ty + 8 * r) * NC + n0 + tx];
    __syncthreads();
#pragma unroll
    for (int r = 0; r < 4; r++) {
        float v = tile[tx][ty + 8 * r];
        dst[(size_t)(n0 + ty + 8 * r) * K + k0 + tx] = __float2half_rn(v);
    }
}

// ======================= 1a) Q/K projection GEMM + RoPE epilogue ============
__global__ __launch_bounds__(256, 2) void mm_proj_kernel(
    const float* __restrict__ cosr, const float* __restrict__ sinr)
{
    extern __shared__ __align__(128) char smem[];
    uint32_t sb = smem_to_u32(smem);
    const int mode = blockIdx.z;   // 0=Q, 1=K
    const int bm = blockIdx.y * 128, bn = blockIdx.x * 128;
    const __nv_bfloat16* Ah = g_Xh + (size_t)bm * Dm;
    const __nv_bfloat16* Al = g_Xl + (size_t)bm * Dm;
    const __nv_bfloat16* Bh = g_WTh + ((size_t)mode * Ff + bn) * Dm;
    const __nv_bfloat16* Bl = g_WTl + ((size_t)mode * Ff + bn) * Dm;
    float acc[4][4][4];
    gemm_mma(Ah, Al, Dm, Bh, Bl, Dm, Dm, sb, acc);

    const int t = threadIdx.x, lane = t & 31, w = t >> 5, wm = w & 1, wn = w >> 1;
    __nv_bfloat16* OH = (mode == 0) ? g_Qh : g_Kh;
    __nv_bfloat16* OL = (mode == 0) ? g_Ql : g_Kl;
#pragma unroll
    for (int mi = 0; mi < 4; mi++)
#pragma unroll
        for (int ni = 0; ni < 4; ni++) {
            int m0 = bm + wm * 64 + mi * 16 + (lane >> 2);
            int c = bn + wn * 32 + ni * 8 + ((lane & 3) << 1);
#pragma unroll
            for (int half = 0; half < 2; half++) {
                int m = m0 + half * 8;
                int n = m & (Nseq - 1);
                float cr0 = cosr[(size_t)n * Ff + c];
                float sr0 = sinr[(size_t)n * Ff + c];
                float cr1 = cosr[(size_t)n * Ff + c + 1];
                float sr1 = sinr[(size_t)n * Ff + c + 1];
                float e = acc[mi][ni][half * 2];
                float o = acc[mi][ni][half * 2 + 1];
                float oe = e * cr0 - o * sr0;
                float oo = o * cr1 + e * sr1;
                unsigned hw, lw;
                split_pair(oe, oo, hw, lw);
                *(unsigned*)&OH[(size_t)m * Ff + c] = hw;
                *(unsigned*)&OL[(size_t)m * Ff + c] = lw;
            }
        }
}

// ======================= 1b) V projection (fp16 1-pass) + bias + transpose ==
__global__ __launch_bounds__(256, 2) void mm_vproj_kernel(const float* __restrict__ bv)
{
    extern __shared__ __align__(128) char smem[];
    uint32_t sb = smem_to_u32(smem);
    const int bm = blockIdx.y * 128, bn = blockIdx.x * 128;
    const __half* Aa = g_X16h + (size_t)bm * Dm;
    const __half* Bv = g_WvT16 + (size_t)bn * Dm;
    float acc[4][4][4];
    gemm_mma_1p(Aa, Dm, Bv, Dm, Dm, sb, acc);

    const int t = threadIdx.x, lane = t & 31, w = t >> 5, wm = w & 1, wn = w >> 1;
    __syncthreads();                    // all MMAs done -> reuse stage smem
    __half* s16 = (__half*)smem;        // [128 f][136 stride] transposed tile
#pragma unroll
    for (int mi = 0; mi < 4; mi++)
#pragma unroll
        for (int ni = 0; ni < 4; ni++) {
            int ml = wm * 64 + mi * 16 + (lane >> 2);
            int cl = wn * 32 + ni * 8 + ((lane & 3) << 1);
            float b0 = bv[bn + cl], b1 = bv[bn + cl + 1];
#pragma unroll
            for (int half = 0; half < 2; half++) {
                int m2 = ml + half * 8;
                s16[cl * 136 + m2]       = __float2half_rn(acc[mi][ni][half * 2] + b0);
                s16[(cl + 1) * 136 + m2] = __float2half_rn(acc[mi][ni][half * 2 + 1] + b1);
            }
        }
    __syncthreads();
    const int b = bm >> 11, tok0 = bm & (Nseq - 1);
    const int h = bn >> 9, f0 = bn & (DHd - 1);
    __half* dst = g_VT + ((size_t)(b * Hh + h) * DHd + f0) * Nseq + tok0;
#pragma unroll
    for (int i = 0; i < 8; i++) {
        int u = t + (i << 8);           // 0..2047
        int f = u >> 4, mg = (u & 15) << 3;
        uint4 v = *(uint4*)&s16[f * 136 + mg];
        *(uint4*)(dst + (size_t)f * Nseq + mg) = v;
    }
}

// ======================= 2) S = Q K^T (triangular grid) =====================
__global__ __launch_bounds__(256, 2) void mm_score_kernel() {
    const int idx = blockIdx.x;          // 0..135
    int iy = (int)((sqrtf(8.0f * idx + 1.0f) - 1.0f) * 0.5f);
    while ((iy + 1) * (iy + 2) / 2 <= idx) iy++;
    while (iy * (iy + 1) / 2 > idx) iy--;
    const int jx = idx - iy * (iy + 1) / 2;

    extern __shared__ __align__(128) char smem[];
    uint32_t sb = smem_to_u32(smem);
    const int bh = blockIdx.z, b = bh >> 3, h = bh & 7;
    const int i0 = iy * 128, j0 = jx * 128;
    const __nv_bfloat16* Ah = g_Qh + (size_t)(b * Nseq + i0) * Ff + h * DHd;
    const __nv_bfloat16* Al = g_Ql + (size_t)(b * Nseq + i0) * Ff + h * DHd;
    const __nv_bfloat16* Bh = g_Kh + (size_t)(b * Nseq + j0) * Ff + h * DHd;
    const __nv_bfloat16* Bl = g_Kl + (size_t)(b * Nseq + j0) * Ff + h * DHd;
    float acc[4][4][4];
    gemm_mma(Ah, Al, Ff, Bh, Bl, Ff, DHd, sb, acc);

    const int t = threadIdx.x, lane = t & 31, w = t >> 5, wm = w & 1, wn = w >> 1;
    float* Sp = g_S + (size_t)bh * Nseq * Nseq;
#pragma unroll
    for (int mi = 0; mi < 4; mi++)
#pragma unroll
        for (int ni = 0; ni < 4; ni++) {
            int m = i0 + wm * 64 + mi * 16 + (lane >> 2);
            int nn = j0 + wn * 32 + ni * 8 + ((lane & 3) << 1);
            *(float2*)&Sp[(size_t)m * Nseq + nn] = make_float2(acc[mi][ni][0], acc[mi][ni][1]);
            *(float2*)&Sp[(size_t)(m + 8) * Nseq + nn] = make_float2(acc[mi][ni][2], acc[mi][ni][3]);
        }
}

// ======================= 3) causal row softmax -> P fp16 hi/lo ==============
__global__ __launch_bounds__(256) void softmax_kernel() {
    const int rgl = blockIdx.x;
    const int bh = rgl >> 11, i = rgl & (Nseq - 1);
    const size_t base = (size_t)bh * Nseq * Nseq + (size_t)i * Nseq;
    const float* row = g_S + base;
    const int Lz = ((i >> 7) + 1) << 7;         // row span actually written
    const int t = threadIdx.x;

    float v[8];
    float mx = -1e30f;
    int nit = 0;
#pragma unroll
    for (int it = 0; it < 2; it++) {
        int j = (t << 2) + (it << 10);
        if (j < Lz) {
            float4 x4 = *(const float4*)(row + j);
            v[it * 4 + 0] = (j + 0 <= i) ? x4.x : -1e30f;
            v[it * 4 + 1] = (j + 1 <= i) ? x4.y : -1e30f;
            v[it * 4 + 2] = (j + 2 <= i) ? x4.z : -1e30f;
            v[it * 4 + 3] = (j + 3 <= i) ? x4.w : -1e30f;
#pragma unroll
            for (int q = 0; q < 4; q++) mx = fmaxf(mx, v[it * 4 + q]);
            nit = it + 1;
        }
    }

    __shared__ float red[256];
    red[t] = mx; __syncthreads();
    for (int s = 128; s > 0; s >>= 1) { if (t < s) red[t] = fmaxf(red[t], red[t + s]); __syncthreads(); }
    mx = red[0]; __syncthreads();

    float sum = 0.f;
    for (int it = 0; it < nit; it++)
#pragma unroll
        for (int q = 0; q < 4; q++) {
            float p = (v[it * 4 + q] > -1e29f) ? __expf(v[it * 4 + q] - mx) : 0.f;
            v[it * 4 + q] = p;
            sum += p;
        }
    red[t] = sum; __syncthreads();
    for (int s = 128; s > 0; s >>= 1) { if (t < s) red[t] += red[t + s]; __syncthreads(); }
    const float inv = 1.0f / red[0];

    for (int it = 0; it < nit; it++) {
        int j = (t << 2) + (it << 10);
        float p0 = v[it * 4 + 0] * inv, p1 = v[it * 4 + 1] * inv;
        float p2 = v[it * 4 + 2] * inv, p3 = v[it * 4 + 3] * inv;
        unsigned h01, l01, h23, l23;
        split_pair16(p0, p1, h01, l01);
        split_pair16(p2, p3, h23, l23);
        *(uint2*)&g_Ph[base + j] = make_uint2(h01, h23);
        *(uint2*)&g_Pl[base + j] = make_uint2(l01, l23);
    }
}

// ======================= 4) Yh = P @ V (fp16 2-pass, heavy blocks first) ====
__global__ __launch_bounds__(256, 2) void mm_pv_kernel() {
    extern __shared__ __align__(128) char smem[];
    uint32_t sb = smem_to_u32(smem);
    const int bh = blockIdx.z;
    const int i0 = (15 - blockIdx.y) * 128;     // longest CTAs launch first
    const int n0 = blockIdx.x * 128;
    const __half* Ph = g_Ph + (size_t)bh * Nseq * Nseq + (size_t)i0 * Nseq;
    const __half* Pl = g_Pl + (size_t)bh * Nseq * Nseq + (size_t)i0 * Nseq;
    const __half* Vv = g_VT + (size_t)bh * DHd * Nseq + (size_t)n0 * Nseq;
    float acc[4][4][4];
    gemm_mma_pv(Ph, Pl, Nseq, Vv, Nseq, i0 + 128, sb, acc);

    const int t = threadIdx.x, lane = t & 31, w = t >> 5, wm = w & 1, wn = w >> 1;
    float* Yp = g_YH + (size_t)bh * Nseq * Dm;
#pragma unroll
    for (int mi = 0; mi < 4; mi++)
#pragma unroll
        for (int ni = 0; ni < 4; ni++) {
            int m = i0 + wm * 64 + mi * 16 + (lane >> 2);
            int nn = n0 + wn * 32 + ni * 8 + ((lane & 3) << 1);
            *(float2*)&Yp[(size_t)m * Dm + nn] = make_float2(acc[mi][ni][0], acc[mi][ni][1]);
            *(float2*)&Yp[(size_t)(m + 8) * Dm + nn] = make_float2(acc[mi][ni][2], acc[mi][ni][3]);
        }
}

// ======================= 5) head-sum + QuickGELU + fp16 =====================
__global__ __launch_bounds__(256) void reduce_kernel() {
    int idx = blockIdx.x * 256 + threadIdx.x;
    int m = idx >> 7;
    int c4 = (idx & 127) * 4;
    int b = m >> 11, n = m & (Nseq - 1);
    float4 s = make_float4(0.f, 0.f, 0.f, 0.f);
#pragma unroll
    for (int h = 0; h < Hh; h++) {
        const float4 v = *(const float4*)(g_YH + (size_t)((b * Hh + h) * Nseq + n) * Dm + c4);
        s.x += v.x; s.y += v.y; s.z += v.z; s.w += v.w;
    }
    s.x = s.x / (1.f + __expf(-1.702f * s.x));
    s.y = s.y / (1.f + __expf(-1.702f * s.y));
    s.z = s.z / (1.f + __expf(-1.702f * s.z));
    s.w = s.w / (1.f + __expf(-1.702f * s.w));
    *(uint2*)(g_G16h + (size_t)m * Dm + c4) =
        make_uint2(pack16(s.x, s.y), pack16(s.z, s.w));
}

// ======================= 6) output projection (fp16 1-pass) =================
__global__ __launch_bounds__(256, 2) void mm_out_kernel(const float* __restrict__ bo,
                                                        float* __restrict__ Outp) {
    extern __shared__ __align__(128) char smem[];
    uint32_t sb = smem_to_u32(smem);
    const int bm = blockIdx.y * 128, bn = blockIdx.x * 128;
    const __half* Aa = g_G16h + (size_t)bm * Dm;
    const __half* Bo = g_WoT16 + (size_t)bn * Dm;
    float acc[4][4][4];
    gemm_mma_1p(Aa, Dm, Bo, Dm, Dm, sb, acc);

    const int t = threadIdx.x, lane = t & 31, w = t >> 5, wm = w & 1, wn = w >> 1;
#pragma unroll
    for (int mi = 0; mi < 4; mi++)
#pragma unroll
        for (int ni = 0; ni < 4; ni++) {
            int m = bm + wm * 64 + mi * 16 + (lane >> 2);
            int c = bn + wn * 32 + ni * 8 + ((lane & 3) << 1);
            float b0 = bo[c], b1 = bo[c + 1];
            *(float2*)&Outp[(size_t)m * Dm + c] =
                make_float2(acc[mi][ni][0] + b0, acc[mi][ni][1] + b1);
            *(float2*)&Outp[(size_t)(m + 8) * Dm + c] =
                make_float2(acc[mi][ni][2] + b0, acc[mi][ni][3] + b1);
        }
}

// ======================= launch =============================================
extern "C" void kernel_launch(void* const* d_in, const int* in_sizes, int n_in,
                              void* d_out, int out_size)
{
    const float* x    = (const float*)d_in[0];
    const float* cosr = (const float*)d_in[1];
    const float* sinr = (const float*)d_in[2];
    // d_in[3] = target_mask (causal tril; handled analytically)
    const float* Wq   = (const float*)d_in[4];
    const float* Wk   = (const float*)d_in[5];
    const float* Wv   = (const float*)d_in[6];
    const float* bv   = (const float*)d_in[7];
    const float* Wo   = (const float*)d_in[8];
    const float* bo   = (const float*)d_in[9];
    float* out = (float*)d_out;

    cudaFuncSetAttribute(mm_proj_kernel,  cudaFuncAttributeMaxDynamicSharedMemorySize, GEMM_SMEM);
    cudaFuncSetAttribute(mm_vproj_kernel, cudaFuncAttributeMaxDynamicSharedMemorySize, P1_SMEM);
    cudaFuncSetAttribute(mm_score_kernel, cudaFuncAttributeMaxDynamicSharedMemorySize, GEMM_SMEM);
    cudaFuncSetAttribute(mm_pv_kernel,    cudaFuncAttributeMaxDynamicSharedMemorySize, PV_SMEM);
    cudaFuncSetAttribute(mm_out_kernel,   cudaFuncAttributeMaxDynamicSharedMemorySize, P1_SMEM);

    __half *wvt16, *wot16;
    cudaGetSymbolAddress((void**)&wvt16, g_WvT16);
    cudaGetSymbolAddress((void**)&wot16, g_WoT16);

    xc_kernel<<<2048, 256>>>(x);
    wtqk_kernel<<<dim3(128, 16, 2), dim3(32, 8)>>>(Wq, Wk);
    wt16_kernel<<<dim3(128, 16), dim3(32, 8)>>>(Wv, wvt16, Dm, Ff);
    wt16_kernel<<<dim3(16, 16), dim3(32, 8)>>>(Wo, wot16, Dm, Dm);
    mm_proj_kernel<<<dim3(32, 32, 2), 256, GEMM_SMEM>>>(cosr, sinr);
    mm_vproj_kernel<<<dim3(32, 32), 256, P1_SMEM>>>(bv);
    mm_score_kernel<<<dim3(136, 1, BH), 256, GEMM_SMEM>>>();
    softmax_kernel<<<BH * Nseq, 256>>>();
    mm_pv_kernel<<<dim3(4, 16, BH), 256, PV_SMEM>>>();
    reduce_kernel<<<2048, 256>>>();
    mm_out_kernel<<<dim3(4, 32), 256, P1_SMEM>>>(bo, out);
}